// round 10
// baseline (speedup 1.0000x reference)
#include <cuda_runtime.h>
#include <cuda_fp16.h>
#include <cstdint>
#include <cstddef>

// ---------------- problem constants ----------------
#define NE    8
#define D_IN  2048
#define H_FF  5632
#define T_TOK 8192
#define PAIRS 16384
#define XROWS (PAIRS + 128)      // padded so GEMM tiles never read OOB

// ---------------- GEMM tiling ----------------
#define BM 128
#define BN 256
#define BK 64
#define MAX_TILES 136            // sum_e ceil(c_e/128) <= 128 + 8
#define GEMM_THREADS 512         // 16 warps, warp tile 64x32
#define NSTAGES 4
#define A_BYTES (BM * BK * 2)    // 16384
#define B_BYTES (BN * BK * 2)    // 32768
#define STAGE_BYTES (A_BYTES + B_BYTES)       // 49152
#define SMEM_TOTAL (NSTAGES * STAGE_BYTES)    // 196608

#define G1_YTILES (H_FF / 128)   // 44
#define CONVUP_BLOCKS 4096
#define ZERO_BLOCKS 512

// ---------------- device scratch (static globals; no allocation) ----------------
__device__ __half g_wup[(size_t)NE * 2 * H_FF * D_IN];   // fp16 gate/up INTERLEAVED (row 2h=gate h, 2h+1=up h)
__device__ __half g_wdn[(size_t)NE * D_IN * H_FF];       // fp16 down weights
__device__ __half g_xh [(size_t)XROWS * D_IN];           // gathered fp16 inputs (sorted by expert)
__device__ __half g_act[(size_t)XROWS * H_FF];           // SwiGLU activations
__device__ int   g_cur[NE];
__device__ int   g_off[NE];
__device__ int   g_rtok[PAIRS];
__device__ float g_rw  [PAIRS];
__device__ int   g_te [MAX_TILES];
__device__ int   g_tm0[MAX_TILES];
__device__ int   g_tm1[MAX_TILES];
__device__ int   g_ntiles;

// ---------------- PTX helpers ----------------
__device__ __forceinline__ uint32_t smem_u32(const void* p) {
    uint32_t a;
    asm("{ .reg .u64 t; cvta.to.shared.u64 t, %1; cvt.u32.u64 %0, t; }" : "=r"(a) : "l"(p));
    return a;
}
__device__ __forceinline__ void cp_async16(uint32_t dst, const void* src) {
    asm volatile("cp.async.cg.shared.global [%0], [%1], 16;" :: "r"(dst), "l"(src));
}
__device__ __forceinline__ void cp_commit() { asm volatile("cp.async.commit_group;" ::: "memory"); }
__device__ __forceinline__ void cp_wait0()  { asm volatile("cp.async.wait_group 0;" ::: "memory"); }

__device__ __forceinline__ void ldsm4(uint32_t* r, uint32_t addr) {
    asm volatile("ldmatrix.sync.aligned.m8n8.x4.shared.b16 {%0,%1,%2,%3}, [%4];"
                 : "=r"(r[0]), "=r"(r[1]), "=r"(r[2]), "=r"(r[3]) : "r"(addr));
}
__device__ __forceinline__ void mma16816(float* c, const uint32_t* a, uint32_t b0, uint32_t b1) {
    asm volatile(
        "mma.sync.aligned.m16n8k16.row.col.f32.f16.f16.f32 "
        "{%0,%1,%2,%3}, {%4,%5,%6,%7}, {%8,%9}, {%0,%1,%2,%3};"
        : "+f"(c[0]), "+f"(c[1]), "+f"(c[2]), "+f"(c[3])
        : "r"(a[0]), "r"(a[1]), "r"(a[2]), "r"(a[3]), "r"(b0), "r"(b1));
}
__device__ __forceinline__ void redg_v2(float* p, float a, float b) {
    asm volatile("red.global.add.v2.f32 [%0], {%1, %2};" :: "l"(p), "f"(a), "f"(b) : "memory");
}
__device__ __forceinline__ uint2 cvt2(float4 v) {
    __half2 a = __floats2half2_rn(v.x, v.y);
    __half2 b = __floats2half2_rn(v.z, v.w);
    uint2 o;
    o.x = *reinterpret_cast<uint32_t*>(&a);
    o.y = *reinterpret_cast<uint32_t*>(&b);
    return o;
}

// ---------------- launch #1: histogram + offsets + tile table + cursors ----------------
__global__ void k_hist(const int* __restrict__ ids) {
    __shared__ int h[NE];
    int tid = threadIdx.x;
    if (tid < NE) h[tid] = 0;
    __syncthreads();
    for (int i = tid; i < PAIRS; i += 1024) atomicAdd(&h[ids[i]], 1);
    __syncthreads();
    if (tid < NE) g_cur[tid] = 0;
    if (tid == 0) {
        int off = 0, slot = 0;
        for (int e = 0; e < NE; e++) {
            g_off[e] = off;
            int c = h[e];
            for (int m = 0; m < c; m += BM) {
                g_te[slot]  = e;
                g_tm0[slot] = off + m;
                g_tm1[slot] = off + ((m + BM < c) ? (m + BM) : c);
                slot++;
            }
            off += c;
        }
        g_ntiles = slot;
    }
}

// ---------------- launch #2: token scatter + up-weight convert (interleaved) + zero(out) ------
__global__ void k_prep(const float* __restrict__ x, const float* __restrict__ tw,
                       const int* __restrict__ ids, const float* __restrict__ sup,
                       float* __restrict__ out) {
    if (blockIdx.x < T_TOK) {
        int t = blockIdx.x;                 // token: handle both top-k slots, read x once
        __shared__ int spos[2];
        if (threadIdx.x < 2) {
            int p   = 2 * t + threadIdx.x;
            int e   = ids[p];
            int pos = g_off[e] + atomicAdd(&g_cur[e], 1);
            g_rtok[pos] = t;
            g_rw[pos]   = tw[p];
            spos[threadIdx.x] = pos;
        }
        __syncthreads();
        int p0 = spos[0], p1 = spos[1];
        const float4* src = (const float4*)(x + (size_t)t * D_IN);
        uint2* d0 = (uint2*)(g_xh + (size_t)p0 * D_IN);
        uint2* d1 = (uint2*)(g_xh + (size_t)p1 * D_IN);
        for (int i = threadIdx.x; i < D_IN / 4; i += 256) {
            uint2 v = cvt2(src[i]);
            d0[i] = v;
            d1[i] = v;
        }
    } else if (blockIdx.x < T_TOK + CONVUP_BLOCKS) {
        // convert + interleave, row-based (no 64-bit division):
        // src row r (within expert e, r in [0,2H)): dst row = (r < H) ? 2r : 2(r-H)+1
        const int NR = NE * 2 * H_FF;            // 90112 rows
        const int ROW4 = D_IN / 4;               // 512 float4 per row
        const int tid = threadIdx.x;
        for (int row = blockIdx.x - T_TOK; row < NR; row += CONVUP_BLOCKS) {
            int e = row / (2 * H_FF);            // constant divide (mul-shift)
            int r = row - e * (2 * H_FF);
            int dr = (r < H_FF) ? (2 * r) : (2 * (r - H_FF) + 1);
            const float4* s = (const float4*)sup + (size_t)row * ROW4;
            uint2* d = (uint2*)g_wup + ((size_t)e * (2 * H_FF) + dr) * ROW4;
            d[tid]       = cvt2(s[tid]);
            d[tid + 256] = cvt2(s[tid + 256]);
        }
    } else {
        size_t n4 = ((size_t)T_TOK * D_IN) >> 2;
        float4 z = make_float4(0.f, 0.f, 0.f, 0.f);
        size_t stride = (size_t)ZERO_BLOCKS * 256;
        for (size_t i = (size_t)(blockIdx.x - T_TOK - CONVUP_BLOCKS) * 256 + threadIdx.x; i < n4; i += stride)
            ((float4*)out)[i] = z;
    }
}

// ---------------- grouped GEMM (mma.sync m16n8k16, 4-stage cp.async, pairwise barrier) --------
// 512 threads, CTA tile 128x256x64, warp tile 64x32 (wm in {0,1}, wn in {0..7}).
// G1: blockIdx.y == 0 -> down-weight convert ride-along (scheduled FIRST, hides under tensor waves).
//     blockIdx.y in [1,44] -> GEMM tile y-1: B = g_wup (interleaved) rows (y-1)*256..+255;
//     lane accum pairs = (gate,up) of same h -> SwiGLU -> g_act.
// G2: B = g_wdn[e] rows y*256..+255 -> w * y red.v2 into out.
template<bool G1>
__global__ void __launch_bounds__(GEMM_THREADS, 1) k_gemm(float* __restrict__ out,
                                                          const float* __restrict__ sdn) {
    if (G1 && blockIdx.y == 0) {
        // down-weight conversion, lowest block IDs -> scheduled in the first wave,
        // its DRAM traffic overlaps G1's tensor-bound GEMM waves
        const size_t ndn4 = ((size_t)NE * D_IN * H_FF) >> 2;
        size_t stride = (size_t)gridDim.x * GEMM_THREADS;
        for (size_t i = (size_t)blockIdx.x * GEMM_THREADS + threadIdx.x; i < ndn4; i += stride)
            ((uint2*)g_wdn)[i] = cvt2(((const float4*)sdn)[i]);
        return;
    }
    extern __shared__ char smem[];
    const int slot = blockIdx.x;
    if (slot >= g_ntiles) return;

    const int tid = threadIdx.x;
    const int wid = tid >> 5;
    const int lid = tid & 31;
    const int wm  = wid & 1;       // 2 M-tiles of 64
    const int wn  = wid >> 1;      // 8 N-tiles of 32

    const int ytile = G1 ? (blockIdx.y - 1) : blockIdx.y;

    const int e  = g_te[slot];
    const int m0 = g_tm0[slot];
    const int m1 = g_tm1[slot];
    constexpr int KTOT   = G1 ? D_IN : H_FF;
    constexpr int KITERS = KTOT / BK;   // 32 / 88 (both even)

    const __half* __restrict__ A  = G1 ? g_xh : g_act;
    const __half* __restrict__ Bw = G1 ? g_wup : g_wdn;

    const uint32_t sb = smem_u32(smem);

    // ---- cp.async addressing: per-thread constants (512 thr)
    const int ch = tid & 7;               // 16B chunk within 128B row
    const int br = tid >> 3;              // base row (0..63); iterations add 64
    const uint32_t swx   = (uint32_t)((ch ^ (br & 7)) << 4);
    const uint32_t a_dst = (uint32_t)br * 128 + swx;            // + i*8192, i in {0,1}
    const uint32_t b_dst = A_BYTES + (uint32_t)br * 128 + swx;  // + i*8192, i in {0..3}

    const size_t ebase = G1 ? ((size_t)e * (2 * H_FF)) : ((size_t)e * D_IN);
    const int    n0r   = ytile * 256;          // first B row (interleaved rows for G1)
    const __half* a_base = A  + (size_t)(m0 + br) * KTOT + ch * 8;
    const __half* b_base = Bw + (ebase + n0r + br) * KTOT + ch * 8;

    auto load_stage = [&](int s, int kc) {
        uint32_t base = sb + s * STAGE_BYTES;
        int koff = kc * BK;
        #pragma unroll
        for (int i = 0; i < 2; i++)
            cp_async16(base + a_dst + i * 8192, a_base + (size_t)i * 64 * KTOT + koff);
        #pragma unroll
        for (int i = 0; i < 4; i++)
            cp_async16(base + b_dst + i * 8192, b_base + (size_t)i * 64 * KTOT + koff);
    };

    // ---- ldmatrix per-lane address pieces
    const int lrx = lid & 7;
    uint32_t a_rowoff[4], b_rowoff[2];
    #pragma unroll
    for (int mb = 0; mb < 4; mb++)
        a_rowoff[mb] = (uint32_t)(wm * 64 + mb * 16 + (lid & 15)) * 128;
    #pragma unroll
    for (int nb2 = 0; nb2 < 2; nb2++)
        b_rowoff[nb2] = A_BYTES + (uint32_t)(wn * 32 + nb2 * 16 + ((lid >> 4) << 3) + (lid & 7)) * 128;
    const int ahi = lid >> 4;            // A chunk hi bit
    const int bhi = (lid >> 3) & 1;      // B chunk hi bit

    float c[4][4][4];
    #pragma unroll
    for (int mb = 0; mb < 4; mb++)
        #pragma unroll
        for (int nb = 0; nb < 4; nb++)
            #pragma unroll
            for (int j = 0; j < 4; j++) c[mb][nb][j] = 0.f;

    auto compute_ktile = [&](int s) {
        const uint32_t stg = sb + s * STAGE_BYTES;
        #pragma unroll
        for (int ks = 0; ks < 4; ks++) {
            uint32_t a[4][4], b[2][4];
            #pragma unroll
            for (int mb = 0; mb < 4; mb++)
                ldsm4(a[mb], stg + a_rowoff[mb] + (uint32_t)(((ks * 2 + ahi) ^ lrx) << 4));
            #pragma unroll
            for (int nb2 = 0; nb2 < 2; nb2++)
                ldsm4(b[nb2], stg + b_rowoff[nb2] + (uint32_t)(((ks * 2 + bhi) ^ lrx) << 4));
            #pragma unroll
            for (int mb = 0; mb < 4; mb++) {
                #pragma unroll
                for (int nb = 0; nb < 4; nb++)
                    mma16816(c[mb][nb], a[mb], b[nb >> 1][(nb & 1) * 2], b[nb >> 1][(nb & 1) * 2 + 1]);
            }
        }
    };

    // ---- prologue: 2 stages in flight
    load_stage(0, 0); cp_commit();
    load_stage(1, 1); cp_commit();

    // ---- pairwise mainloop: one barrier per 2 k-tiles
    for (int kt = 0; kt < KITERS; kt += 2) {
        cp_wait0();
        __syncthreads();
        if (kt + 2 < KITERS) { load_stage((kt + 2) & 3, kt + 2); cp_commit(); }
        if (kt + 3 < KITERS) { load_stage((kt + 3) & 3, kt + 3); cp_commit(); }
        compute_ktile(kt & 3);
        compute_ktile((kt + 1) & 3);
    }
    __syncthreads();   // protect smem reuse by epilogue staging

    // ---- epilogue
    if (G1) {
        // SwiGLU -> stage fp16 to smem [128 rows][128 halfs, stride 136] -> coalesced copy out
        __half* acts = (__half*)smem;
        const int n0h = ytile * 128;
        #pragma unroll
        for (int mb = 0; mb < 4; mb++) {
            #pragma unroll
            for (int nb = 0; nb < 4; nb++) {
                int hl = wn * 16 + nb * 4 + (lid & 3);
                int r0 = wm * 64 + mb * 16 + (lid >> 2);
                float g0 = c[mb][nb][0], u0 = c[mb][nb][1];
                float g1 = c[mb][nb][2], u1 = c[mb][nb][3];
                float v0 = u0 * g0 / (1.f + __expf(-g0));
                float v1 = u1 * g1 / (1.f + __expf(-g1));
                acts[r0 * 136 + hl]       = __float2half_rn(v0);
                acts[(r0 + 8) * 136 + hl] = __float2half_rn(v1);
            }
        }
        __syncthreads();
        for (int idx = tid; idx < 128 * 16; idx += GEMM_THREADS) {
            int row = idx >> 4, q = idx & 15;
            if (m0 + row < m1) {
                uint4 v = *(const uint4*)((const char*)smem + row * 272 + q * 16);
                *(uint4*)(g_act + (size_t)(m0 + row) * H_FF + n0h + q * 8) = v;
            }
        }
    } else {
        const int n0 = ytile * 256;
        #pragma unroll
        for (int mb = 0; mb < 4; mb++) {
            int r0 = m0 + wm * 64 + mb * 16 + (lid >> 2);
            int r1 = r0 + 8;
            bool v0 = r0 < m1, v1 = r1 < m1;
            int tk0 = 0, tk1 = 0; float w0 = 0.f, w1 = 0.f;
            if (v0) { tk0 = g_rtok[r0]; w0 = g_rw[r0]; }
            if (v1) { tk1 = g_rtok[r1]; w1 = g_rw[r1]; }
            float* p0 = out + (size_t)tk0 * D_IN;
            float* p1 = out + (size_t)tk1 * D_IN;
            #pragma unroll
            for (int nb = 0; nb < 4; nb++) {
                int col = n0 + wn * 32 + nb * 8 + (lid & 3) * 2;
                if (v0) redg_v2(p0 + col, w0 * c[mb][nb][0], w0 * c[mb][nb][1]);
                if (v1) redg_v2(p1 + col, w1 * c[mb][nb][2], w1 * c[mb][nb][3]);
            }
        }
    }
}

// ---------------- launch ----------------
extern "C" void kernel_launch(void* const* d_in, const int* in_sizes, int n_in,
                              void* d_out, int out_size) {
    const float* x   = (const float*)d_in[0];   // [8192, 2048]
    const float* tw  = (const float*)d_in[1];   // [8192, 2]
    const float* wup = (const float*)d_in[2];   // [8, 11264, 2048]
    const float* wdn = (const float*)d_in[3];   // [8, 2048, 5632]
    const int*   ids = (const int*)d_in[4];     // [8192, 2]
    float* out = (float*)d_out;                 // [8192, 2048]

    cudaFuncSetAttribute(k_gemm<true>,  cudaFuncAttributeMaxDynamicSharedMemorySize, SMEM_TOTAL);
    cudaFuncSetAttribute(k_gemm<false>, cudaFuncAttributeMaxDynamicSharedMemorySize, SMEM_TOTAL);

    k_hist<<<1, 1024>>>(ids);                                                // #1
    k_prep<<<T_TOK + CONVUP_BLOCKS + ZERO_BLOCKS, 256>>>(x, tw, ids, wup, out); // #2
    k_gemm<true ><<<dim3(MAX_TILES, G1_YTILES + 1), GEMM_THREADS, SMEM_TOTAL>>>(nullptr, wdn); // #3
    k_gemm<false><<<dim3(MAX_TILES, D_IN / 256), GEMM_THREADS, SMEM_TOTAL>>>(out, nullptr);    // #4 (profiled)
}

// round 11
// speedup vs baseline: 1.0170x; 1.0170x over previous
#include <cuda_runtime.h>
#include <cuda_fp16.h>
#include <cstdint>
#include <cstddef>

// ---------------- problem constants ----------------
#define NE    8
#define D_IN  2048
#define H_FF  5632
#define T_TOK 8192
#define PAIRS 16384
#define XROWS (PAIRS + 128)      // padded so GEMM tiles never read OOB

// ---------------- GEMM tiling ----------------
#define BM 128
#define BN 256
#define BK 64
#define MAX_TILES 136            // sum_e ceil(c_e/128) <= 128 + 8
#define GEMM_THREADS 512         // 16 warps, warp tile 64x32
#define NSTAGES 4
#define A_BYTES (BM * BK * 2)    // 16384
#define B_BYTES (BN * BK * 2)    // 32768
#define STAGE_BYTES (A_BYTES + B_BYTES)       // 49152
#define SMEM_TOTAL (NSTAGES * STAGE_BYTES + 64)  // stages + 8 mbarriers

#define G1_YTILES (H_FF / 128)   // 44
#define CONVUP_BLOCKS 4096
#define ZERO_BLOCKS 512

// ---------------- device scratch (static globals; no allocation) ----------------
__device__ __half g_wup[(size_t)NE * 2 * H_FF * D_IN];   // fp16 gate+up weights (standard layout)
__device__ __half g_wdn[(size_t)NE * D_IN * H_FF];       // fp16 down weights
__device__ __half g_xh [(size_t)XROWS * D_IN];           // gathered fp16 inputs (sorted by expert)
__device__ __half g_act[(size_t)XROWS * H_FF];           // SwiGLU activations
__device__ int   g_cur[NE];
__device__ int   g_off[NE];
__device__ int   g_rtok[PAIRS];
__device__ float g_rw  [PAIRS];
__device__ int   g_te [MAX_TILES];
__device__ int   g_tm0[MAX_TILES];
__device__ int   g_tm1[MAX_TILES];
__device__ int   g_ntiles;

// ---------------- PTX helpers ----------------
__device__ __forceinline__ uint32_t smem_u32(const void* p) {
    uint32_t a;
    asm("{ .reg .u64 t; cvta.to.shared.u64 t, %1; cvt.u32.u64 %0, t; }" : "=r"(a) : "l"(p));
    return a;
}
__device__ __forceinline__ void cp_async16(uint32_t dst, const void* src) {
    asm volatile("cp.async.cg.shared.global [%0], [%1], 16;" :: "r"(dst), "l"(src));
}
__device__ __forceinline__ void mbar_init(uint32_t a, uint32_t cnt) {
    asm volatile("mbarrier.init.shared.b64 [%0], %1;" :: "r"(a), "r"(cnt) : "memory");
}
__device__ __forceinline__ void mbar_arrive(uint32_t a) {
    asm volatile("mbarrier.arrive.shared.b64 _, [%0];" :: "r"(a) : "memory");
}
__device__ __forceinline__ void cp_async_mbar_arrive(uint32_t a) {
    asm volatile("cp.async.mbarrier.arrive.noinc.shared.b64 [%0];" :: "r"(a) : "memory");
}
__device__ __forceinline__ void mbar_wait(uint32_t a, uint32_t parity) {
    uint32_t done;
    asm volatile(
        "{ .reg .pred p; mbarrier.try_wait.parity.acquire.cta.shared::cta.b64 p, [%1], %2; selp.b32 %0,1,0,p; }"
        : "=r"(done) : "r"(a), "r"(parity) : "memory");
    if (!done) {
        asm volatile(
            "{\n\t.reg .pred P1;\n\t"
            "WL_%=:\n\t"
            "mbarrier.try_wait.parity.acquire.cta.shared::cta.b64 P1, [%0], %1, 0x989680;\n\t"
            "@P1 bra.uni WD_%=;\n\t"
            "bra.uni WL_%=;\n\t"
            "WD_%=:\n\t}"
            :: "r"(a), "r"(parity) : "memory");
    }
}
__device__ __forceinline__ void ldsm4(uint32_t* r, uint32_t addr) {
    asm volatile("ldmatrix.sync.aligned.m8n8.x4.shared.b16 {%0,%1,%2,%3}, [%4];"
                 : "=r"(r[0]), "=r"(r[1]), "=r"(r[2]), "=r"(r[3]) : "r"(addr));
}
__device__ __forceinline__ void mma16816(float* c, const uint32_t* a, uint32_t b0, uint32_t b1) {
    asm volatile(
        "mma.sync.aligned.m16n8k16.row.col.f32.f16.f16.f32 "
        "{%0,%1,%2,%3}, {%4,%5,%6,%7}, {%8,%9}, {%0,%1,%2,%3};"
        : "+f"(c[0]), "+f"(c[1]), "+f"(c[2]), "+f"(c[3])
        : "r"(a[0]), "r"(a[1]), "r"(a[2]), "r"(a[3]), "r"(b0), "r"(b1));
}
__device__ __forceinline__ void redg_v2(float* p, float a, float b) {
    asm volatile("red.global.add.v2.f32 [%0], {%1, %2};" :: "l"(p), "f"(a), "f"(b) : "memory");
}
__device__ __forceinline__ uint2 cvt2(float4 v) {
    __half2 a = __floats2half2_rn(v.x, v.y);
    __half2 b = __floats2half2_rn(v.z, v.w);
    uint2 o;
    o.x = *reinterpret_cast<uint32_t*>(&a);
    o.y = *reinterpret_cast<uint32_t*>(&b);
    return o;
}

// ---------------- launch #1: histogram + offsets + tile table + cursors ----------------
__global__ void k_hist(const int* __restrict__ ids) {
    __shared__ int h[NE];
    int tid = threadIdx.x;
    if (tid < NE) h[tid] = 0;
    __syncthreads();
    for (int i = tid; i < PAIRS; i += 1024) atomicAdd(&h[ids[i]], 1);
    __syncthreads();
    if (tid < NE) g_cur[tid] = 0;
    if (tid == 0) {
        int off = 0, slot = 0;
        for (int e = 0; e < NE; e++) {
            g_off[e] = off;
            int c = h[e];
            for (int m = 0; m < c; m += BM) {
                g_te[slot]  = e;
                g_tm0[slot] = off + m;
                g_tm1[slot] = off + ((m + BM < c) ? (m + BM) : c);
                slot++;
            }
            off += c;
        }
        g_ntiles = slot;
    }
}

// ---------------- launch #2: token scatter + linear up-weight convert + zero(out) -------------
__global__ void k_prep(const float* __restrict__ x, const float* __restrict__ tw,
                       const int* __restrict__ ids, const float* __restrict__ sup,
                       float* __restrict__ out) {
    if (blockIdx.x < T_TOK) {
        int t = blockIdx.x;                 // token: handle both top-k slots, read x once
        __shared__ int spos[2];
        if (threadIdx.x < 2) {
            int p   = 2 * t + threadIdx.x;
            int e   = ids[p];
            int pos = g_off[e] + atomicAdd(&g_cur[e], 1);
            g_rtok[pos] = t;
            g_rw[pos]   = tw[p];
            spos[threadIdx.x] = pos;
        }
        __syncthreads();
        int p0 = spos[0], p1 = spos[1];
        const float4* src = (const float4*)(x + (size_t)t * D_IN);
        uint2* d0 = (uint2*)(g_xh + (size_t)p0 * D_IN);
        uint2* d1 = (uint2*)(g_xh + (size_t)p1 * D_IN);
        for (int i = threadIdx.x; i < D_IN / 4; i += 256) {
            uint2 v = cvt2(src[i]);
            d0[i] = v;
            d1[i] = v;
        }
    } else if (blockIdx.x < T_TOK + CONVUP_BLOCKS) {
        const size_t nup4 = ((size_t)NE * 2 * H_FF * D_IN) >> 2;
        size_t stride = (size_t)CONVUP_BLOCKS * 256;
        for (size_t i = (size_t)(blockIdx.x - T_TOK) * 256 + threadIdx.x; i < nup4; i += stride)
            ((uint2*)g_wup)[i] = cvt2(((const float4*)sup)[i]);
    } else {
        size_t n4 = ((size_t)T_TOK * D_IN) >> 2;
        float4 z = make_float4(0.f, 0.f, 0.f, 0.f);
        size_t stride = (size_t)ZERO_BLOCKS * 256;
        for (size_t i = (size_t)(blockIdx.x - T_TOK - CONVUP_BLOCKS) * 256 + threadIdx.x; i < n4; i += stride)
            ((float4*)out)[i] = z;
    }
}

// ---------------- grouped GEMM (mma.sync m16n8k16, 4-stage cp.async + per-stage mbarriers) ----
// 512 threads, CTA tile 128x256x64, warp tile 64x32. NO CTA-wide barrier in the mainloop.
// G1: smem B row r <- weight row (r&1 ? H+h : h), h = y*128 + (r>>1) -- achieved with a single
//     linear base pointer since each load-thread's row parity (br&1) is constant.
//     Lane accum pairs = (gate,up) of same h -> SwiGLU -> g_act. (y == G1_YTILES: down convert.)
// G2: B = g_wdn[e] rows y*256..+255 -> w * y red.v2 into out.
template<bool G1>
__global__ void __launch_bounds__(GEMM_THREADS, 1) k_gemm(float* __restrict__ out,
                                                          const float* __restrict__ sdn) {
    if (G1 && blockIdx.y == G1_YTILES) {
        const size_t ndn4 = ((size_t)NE * D_IN * H_FF) >> 2;
        size_t stride = (size_t)gridDim.x * GEMM_THREADS;
        for (size_t i = (size_t)blockIdx.x * GEMM_THREADS + threadIdx.x; i < ndn4; i += stride)
            ((uint2*)g_wdn)[i] = cvt2(((const float4*)sdn)[i]);
        return;
    }
    extern __shared__ char smem[];
    const int slot = blockIdx.x;
    if (slot >= g_ntiles) return;

    const int tid = threadIdx.x;
    const int wid = tid >> 5;
    const int lid = tid & 31;
    const int wm  = wid & 1;       // 2 M-tiles of 64
    const int wn  = wid >> 1;      // 8 N-tiles of 32

    const int ytile = blockIdx.y;
    const int e  = g_te[slot];
    const int m0 = g_tm0[slot];
    const int m1 = g_tm1[slot];
    constexpr int KTOT   = G1 ? D_IN : H_FF;
    constexpr int KITERS = KTOT / BK;   // 32 / 88
    constexpr int BSTEP  = G1 ? 32 : 64;  // weight-row stride per B chunk

    const __half* __restrict__ A  = G1 ? g_xh : g_act;
    const __half* __restrict__ Bw = G1 ? g_wup : g_wdn;

    const uint32_t sb = smem_u32(smem);
    const uint32_t bb = sb + NSTAGES * STAGE_BYTES;   // mbarriers: full[s]=bb+8s, free[s]=bb+32+8s

    if (tid == 0) {
        #pragma unroll
        for (int s = 0; s < NSTAGES; s++) {
            mbar_init(bb + 8 * s, GEMM_THREADS);        // full[s]
            mbar_init(bb + 32 + 8 * s, GEMM_THREADS);   // free[s]
        }
    }
    __syncthreads();

    // ---- cp.async addressing: per-thread constants
    const int ch = tid & 7;               // 16B chunk within 128B row
    const int br = tid >> 3;              // base smem row (0..63); chunk i adds 64
    const uint32_t swx   = (uint32_t)((ch ^ (br & 7)) << 4);
    const uint32_t a_dst = (uint32_t)br * 128 + swx;            // + i*8192, i in {0,1}
    const uint32_t b_dst = A_BYTES + (uint32_t)br * 128 + swx;  // + i*8192, i in {0..3}

    size_t grow0;
    if (G1) grow0 = (size_t)e * (2 * H_FF) + (size_t)((br & 1) ? H_FF : 0) + ytile * 128 + (br >> 1);
    else    grow0 = (size_t)e * D_IN + (size_t)ytile * 256 + br;
    const __half* a_base = A  + (size_t)(m0 + br) * KTOT + ch * 8;
    const __half* b_base = Bw + grow0 * KTOT + ch * 8;

    auto load_stage = [&](int s, int kc) {
        uint32_t base = sb + s * STAGE_BYTES;
        int koff = kc * BK;
        #pragma unroll
        for (int i = 0; i < 2; i++)
            cp_async16(base + a_dst + i * 8192, a_base + (size_t)i * 64 * KTOT + koff);
        #pragma unroll
        for (int i = 0; i < 4; i++)
            cp_async16(base + b_dst + i * 8192, b_base + (size_t)i * BSTEP * KTOT + koff);
        cp_async_mbar_arrive(bb + 8 * s);
    };

    // ---- ldmatrix per-lane address pieces
    const int lrx = lid & 7;
    uint32_t a_rowoff[4], b_rowoff[2];
    #pragma unroll
    for (int mb = 0; mb < 4; mb++)
        a_rowoff[mb] = (uint32_t)(wm * 64 + mb * 16 + (lid & 15)) * 128;
    #pragma unroll
    for (int nb2 = 0; nb2 < 2; nb2++)
        b_rowoff[nb2] = A_BYTES + (uint32_t)(wn * 32 + nb2 * 16 + ((lid >> 4) << 3) + (lid & 7)) * 128;
    const int ahi = lid >> 4;            // A chunk hi bit
    const int bhi = (lid >> 3) & 1;      // B chunk hi bit

    float c[4][4][4];
    #pragma unroll
    for (int mb = 0; mb < 4; mb++)
        #pragma unroll
        for (int nb = 0; nb < 4; nb++)
            #pragma unroll
            for (int j = 0; j < 4; j++) c[mb][nb][j] = 0.f;

    auto compute_ktile = [&](int s) {
        const uint32_t stg = sb + s * STAGE_BYTES;
        #pragma unroll
        for (int ks = 0; ks < 4; ks++) {
            uint32_t a[4][4], b[2][4];
            #pragma unroll
            for (int mb = 0; mb < 4; mb++)
                ldsm4(a[mb], stg + a_rowoff[mb] + (uint32_t)(((ks * 2 + ahi) ^ lrx) << 4));
            #pragma unroll
            for (int nb2 = 0; nb2 < 2; nb2++)
                ldsm4(b[nb2], stg + b_rowoff[nb2] + (uint32_t)(((ks * 2 + bhi) ^ lrx) << 4));
            #pragma unroll
            for (int mb = 0; mb < 4; mb++) {
                #pragma unroll
                for (int nb = 0; nb < 4; nb++)
                    mma16816(c[mb][nb], a[mb], b[nb >> 1][(nb & 1) * 2], b[nb >> 1][(nb & 1) * 2 + 1]);
            }
        }
    };

    // ---- prologue: 3 stages in flight
    load_stage(0, 0);
    load_stage(1, 1);
    load_stage(2, 2);

    // ---- barrier-free mainloop: per-stage mbarrier handshakes only
    for (int kt = 0; kt < KITERS; kt++) {
        if (kt + 3 < KITERS) {
            int s3 = (kt + 3) & 3;
            if (kt >= 1) mbar_wait(bb + 32 + 8 * s3, ((kt - 1) >> 2) & 1);   // free[s3]
            load_stage(s3, kt + 3);
        }
        int s = kt & 3;
        mbar_wait(bb + 8 * s, (kt >> 2) & 1);                                // full[s]
        compute_ktile(s);
        mbar_arrive(bb + 32 + 8 * s);                                        // free[s]
    }
    __syncthreads();   // protect smem reuse by epilogue staging

    // ---- epilogue
    if (G1) {
        // SwiGLU -> stage fp16 to smem [128 rows][128 halfs, stride 136] -> coalesced copy out
        __half* acts = (__half*)smem;
        const int n0h = ytile * 128;
        #pragma unroll
        for (int mb = 0; mb < 4; mb++) {
            #pragma unroll
            for (int nb = 0; nb < 4; nb++) {
                int hl = wn * 16 + nb * 4 + (lid & 3);
                int r0 = wm * 64 + mb * 16 + (lid >> 2);
                float g0 = c[mb][nb][0], u0 = c[mb][nb][1];
                float g1 = c[mb][nb][2], u1 = c[mb][nb][3];
                float v0 = u0 * g0 / (1.f + __expf(-g0));
                float v1 = u1 * g1 / (1.f + __expf(-g1));
                acts[r0 * 136 + hl]       = __float2half_rn(v0);
                acts[(r0 + 8) * 136 + hl] = __float2half_rn(v1);
            }
        }
        __syncthreads();
        for (int idx = tid; idx < 128 * 16; idx += GEMM_THREADS) {
            int row = idx >> 4, q = idx & 15;
            if (m0 + row < m1) {
                uint4 v = *(const uint4*)((const char*)smem + row * 272 + q * 16);
                *(uint4*)(g_act + (size_t)(m0 + row) * H_FF + n0h + q * 8) = v;
            }
        }
    } else {
        const int n0 = ytile * 256;
        #pragma unroll
        for (int mb = 0; mb < 4; mb++) {
            int r0 = m0 + wm * 64 + mb * 16 + (lid >> 2);
            int r1 = r0 + 8;
            bool v0 = r0 < m1, v1 = r1 < m1;
            int tk0 = 0, tk1 = 0; float w0 = 0.f, w1 = 0.f;
            if (v0) { tk0 = g_rtok[r0]; w0 = g_rw[r0]; }
            if (v1) { tk1 = g_rtok[r1]; w1 = g_rw[r1]; }
            float* p0 = out + (size_t)tk0 * D_IN;
            float* p1 = out + (size_t)tk1 * D_IN;
            #pragma unroll
            for (int nb = 0; nb < 4; nb++) {
                int col = n0 + wn * 32 + nb * 8 + (lid & 3) * 2;
                if (v0) redg_v2(p0 + col, w0 * c[mb][nb][0], w0 * c[mb][nb][1]);
                if (v1) redg_v2(p1 + col, w1 * c[mb][nb][2], w1 * c[mb][nb][3]);
            }
        }
    }
}

// ---------------- launch ----------------
extern "C" void kernel_launch(void* const* d_in, const int* in_sizes, int n_in,
                              void* d_out, int out_size) {
    const float* x   = (const float*)d_in[0];   // [8192, 2048]
    const float* tw  = (const float*)d_in[1];   // [8192, 2]
    const float* wup = (const float*)d_in[2];   // [8, 11264, 2048]
    const float* wdn = (const float*)d_in[3];   // [8, 2048, 5632]
    const int*   ids = (const int*)d_in[4];     // [8192, 2]
    float* out = (float*)d_out;                 // [8192, 2048]

    cudaFuncSetAttribute(k_gemm<true>,  cudaFuncAttributeMaxDynamicSharedMemorySize, SMEM_TOTAL);
    cudaFuncSetAttribute(k_gemm<false>, cudaFuncAttributeMaxDynamicSharedMemorySize, SMEM_TOTAL);

    k_hist<<<1, 1024>>>(ids);                                                   // #1
    k_prep<<<T_TOK + CONVUP_BLOCKS + ZERO_BLOCKS, 256>>>(x, tw, ids, wup, out); // #2
    k_gemm<true ><<<dim3(MAX_TILES, G1_YTILES + 1), GEMM_THREADS, SMEM_TOTAL>>>(nullptr, wdn); // #3
    k_gemm<false><<<dim3(MAX_TILES, D_IN / 256), GEMM_THREADS, SMEM_TOTAL>>>(out, nullptr);    // #4 (profiled)
}